// round 11
// baseline (speedup 1.0000x reference)
#include <cuda_runtime.h>
#include <cuda_bf16.h>

// Problem dims
#define BATCH  64
#define SDIM   4096
#define DDIM   256
#define SCHUNK 512
#define NCHUNK (SDIM / SCHUNK)           // 8
#define NBLK   (BATCH * NCHUNK)          // 512 CTAs, occ 4

#define TROWS  16                        // rows per tile
#define NTILE  (SCHUNK / TROWS)          // 32 tiles per CTA
#define TF4    (TROWS * 64)              // 1024 float4 = 16 KB
#define TBYTES (TROWS * DDIM * 4)        // 16384

// Scratch for cross-CTA partials (no allocation allowed -> device globals)
__device__ float g_acc[NBLK * DDIM];
__device__ float g_sum[NBLK];
__device__ int   g_cnt[BATCH];           // zero-init; re-armed by finalizer

__device__ __forceinline__ float warp_sum(float v) {
    #pragma unroll
    for (int o = 16; o; o >>= 1) v += __shfl_xor_sync(0xffffffffu, v, o);
    return v;
}

// exp(tanh(x)) via tanh(x) = 1 - 2/(e^{2x}+1); saturates correctly at +-1.
// Measured rel_err ~1.0e-6 (R9/R10), same as tanhf path.
__device__ __forceinline__ float exp_tanh(float x) {
    const float t  = __expf(2.f * x);
    const float th = 1.f - __fdividef(2.f, t + 1.f);
    return __expf(th);
}

__device__ __forceinline__ unsigned s2u(const void* p) {
    return (unsigned)__cvta_generic_to_shared(p);
}

__device__ __forceinline__ void mbar_init(unsigned mbar, unsigned count) {
    asm volatile("mbarrier.init.shared.b64 [%0], %1;" :: "r"(mbar), "r"(count) : "memory");
}
__device__ __forceinline__ void mbar_expect_tx(unsigned mbar, unsigned bytes) {
    asm volatile("mbarrier.arrive.expect_tx.shared.b64 _, [%0], %1;"
                 :: "r"(mbar), "r"(bytes) : "memory");
}
__device__ __forceinline__ void mbar_wait(unsigned mbar, unsigned parity) {
    asm volatile(
        "{\n\t"
        ".reg .pred P;\n\t"
        "WAIT_%=: \n\t"
        "mbarrier.try_wait.parity.acquire.cta.shared::cta.b64 P, [%0], %1, 0x989680;\n\t"
        "@P bra.uni DONE_%=;\n\t"
        "bra.uni WAIT_%=;\n\t"
        "DONE_%=: \n\t"
        "}"
        :: "r"(mbar), "r"(parity) : "memory");
}
// 1D bulk TMA: gmem -> smem, completion via mbarrier complete_tx (SASS: UBLKCP)
__device__ __forceinline__ void bulk_g2s(unsigned smem, const void* gmem,
                                         unsigned bytes, unsigned mbar) {
    asm volatile(
        "cp.async.bulk.shared::cluster.global.mbarrier::complete_tx::bytes "
        "[%0], [%1], %2, [%3];"
        :: "r"(smem), "l"(gmem), "r"(bytes), "r"(mbar) : "memory");
}

// ---------------------------------------------------------------------------
// Single pass over memory (268 MB read exactly once):
//   gi = tanh(m·Wm + c_b) in [-1,1] => exp never overflows => softmax needs
//   no running max; accumulate exp(gi)*m and exp(gi) in one sweep.
//
// R11: fill path = TMA bulk copies (1 UBLKCP per 16 KB tile, async proxy)
// instead of ~1k per-thread LSU ops per tile — probes whether the stable
// 70-74% DRAM plateau of all SIMT load paths is an L1tex/LSU service limit.
// Double-buffered; elected-thread issue; mbarrier complete_tx + acquire wait.
// Last CTA per batch finalizes (threadfence-reduction pattern).
// ---------------------------------------------------------------------------
__global__ __launch_bounds__(256, 4)
void att_fused(const float* __restrict__ memory,
               const float* __restrict__ aspect,
               const float* __restrict__ W,
               const float* __restrict__ bias,
               float* __restrict__ out)
{
    __shared__ __align__(1024) float4 tiles[2][TF4];   // 32 KB staging
    __shared__ alignas(8) unsigned long long mbar[2];
    __shared__ float wred[8];
    __shared__ float wsum[8];
    __shared__ float sc;
    __shared__ int   s_old;

    const int tid  = threadIdx.x;
    const int lane = tid & 31;
    const int warp = tid >> 5;
    const int blk  = blockIdx.x;
    const int b    = blk >> 3;           // / NCHUNK
    const int chnk = blk & (NCHUNK - 1);

    const char* gbase = (const char*)(memory
                        + ((long)b * SDIM + (long)chnk * SCHUNK) * DDIM);
    const unsigned mb0 = s2u(&mbar[0]);
    const unsigned mb1 = s2u(&mbar[1]);
    const unsigned st0 = s2u(&tiles[0][0]);
    const unsigned st1 = s2u(&tiles[1][0]);

    // ---- init barriers, launch tiles 0,1 ASAP ----
    if (tid == 0) {
        mbar_init(mb0, 1);
        mbar_init(mb1, 1);
        // fence so the async proxy (TMA) sees the initialized barriers
        asm volatile("fence.proxy.async.shared::cta;" ::: "memory");
        mbar_expect_tx(mb0, TBYTES);
        bulk_g2s(st0, gbase, TBYTES, mb0);
        mbar_expect_tx(mb1, TBYTES);
        bulk_g2s(st1, gbase + TBYTES, TBYTES, mb1);
    }

    // ---- c_b = aspect[b]·Wa + bias (overlaps tile-0 flight) ----
    {
        float v = warp_sum(aspect[b * DDIM + tid] * W[DDIM + tid]);
        if (lane == 0) wred[warp] = v;
        __syncthreads();                  // also orders mbar_init for all threads
        if (tid == 0) {
            float c = bias[0];
            #pragma unroll
            for (int w = 0; w < 8; w++) c += wred[w];
            sc = c;
        }
        __syncthreads();
    }
    const float cb = sc;

    // ---- Wm slice in registers: lane covers d = 4*lane.. and 128+4*lane.. ----
    const float4 wm0 = *reinterpret_cast<const float4*>(W + 4 * lane);
    const float4 wm1 = *reinterpret_cast<const float4*>(W + 128 + 4 * lane);

    float4 a0 = make_float4(0.f, 0.f, 0.f, 0.f);
    float4 a1 = make_float4(0.f, 0.f, 0.f, 0.f);
    float  sw = 0.f;

    for (int t = 0; t < NTILE; t++) {
        const int s = t & 1;
        mbar_wait(s ? mb1 : mb0, (t >> 1) & 1);   // tile t resident (acquire)

        // ---- compute: warp handles tile rows warp and warp+8 ----
        const float4* r0 = &tiles[s][(warp)     * 64];
        const float4* r1 = &tiles[s][(warp + 8) * 64];
        const float4 m00 = r0[lane], m01 = r0[32 + lane];
        const float4 m10 = r1[lane], m11 = r1[32 + lane];

        float d0 = m00.x * wm0.x + m00.y * wm0.y + m00.z * wm0.z + m00.w * wm0.w
                 + m01.x * wm1.x + m01.y * wm1.y + m01.z * wm1.z + m01.w * wm1.w;
        float d1 = m10.x * wm0.x + m10.y * wm0.y + m10.z * wm0.z + m10.w * wm0.w
                 + m11.x * wm1.x + m11.y * wm1.y + m11.z * wm1.z + m11.w * wm1.w;
        d0 = warp_sum(d0);
        d1 = warp_sum(d1);
        const float w0 = exp_tanh(d0 + cb);
        const float w1 = exp_tanh(d1 + cb);

        a0.x += w0 * m00.x + w1 * m10.x;  a0.y += w0 * m00.y + w1 * m10.y;
        a0.z += w0 * m00.z + w1 * m10.z;  a0.w += w0 * m00.w + w1 * m10.w;
        a1.x += w0 * m01.x + w1 * m11.x;  a1.y += w0 * m01.y + w1 * m11.y;
        a1.z += w0 * m01.z + w1 * m11.z;  a1.w += w0 * m01.w + w1 * m11.w;
        sw   += w0 + w1;                  // uniform across lanes post-butterfly

        __syncthreads();                  // slot s free for reuse
        if (tid == 0 && t + 2 < NTILE) {
            const unsigned mb = s ? mb1 : mb0;
            mbar_expect_tx(mb, TBYTES);
            bulk_g2s(s ? st1 : st0, gbase + (long)(t + 2) * TBYTES, TBYTES, mb);
        }
    }

    // ---- deterministic 8-warp combine; slab overlays the dead tiles ----
    __syncthreads();
    float* slab = reinterpret_cast<float*>(tiles);         // [8][DDIM]
    float* my   = slab + warp * DDIM;
    my[4 * lane + 0] = a0.x;  my[4 * lane + 1] = a0.y;
    my[4 * lane + 2] = a0.z;  my[4 * lane + 3] = a0.w;
    my[128 + 4 * lane + 0] = a1.x;  my[128 + 4 * lane + 1] = a1.y;
    my[128 + 4 * lane + 2] = a1.z;  my[128 + 4 * lane + 3] = a1.w;
    if (lane == 0) wsum[warp] = sw;
    __syncthreads();

    {
        float t = 0.f;
        #pragma unroll
        for (int w = 0; w < 8; w++) t += slab[w * DDIM + tid];
        g_acc[blk * DDIM + tid] = t;
        if (tid == 0) {
            float s = 0.f;
            #pragma unroll
            for (int w = 0; w < 8; w++) s += wsum[w];
            g_sum[blk] = s;
        }
    }
    __syncthreads();

    // ---- last-CTA-per-batch finalize ----
    if (tid == 0) {
        __threadfence();
        s_old = atomicAdd(&g_cnt[b], 1);
    }
    __syncthreads();
    if (s_old == NCHUNK - 1) {
        __threadfence();                  // acquire siblings' partials
        float acc = 0.f, s = 0.f;
        #pragma unroll
        for (int c = 0; c < NCHUNK; c++) {
            acc += g_acc[(b * NCHUNK + c) * DDIM + tid];
            s   += g_sum[b * NCHUNK + c];
        }
        out[b * DDIM + tid] = acc / s;
        __syncthreads();
        if (tid == 0) g_cnt[b] = 0;       // re-arm for next graph replay
    }
}

extern "C" void kernel_launch(void* const* d_in, const int* in_sizes, int n_in,
                              void* d_out, int out_size)
{
    // Map inputs by element count:
    //   memory: B*S*D = 67108864, aspect: B*D = 16384, W: 2*D = 512, b: 1
    const float *aspect = nullptr, *memory = nullptr, *W = nullptr, *bias = nullptr;
    for (int i = 0; i < n_in; i++) {
        const long n = (long)in_sizes[i];
        const float* p = (const float*)d_in[i];
        if      (n == (long)BATCH * SDIM * DDIM) memory = p;
        else if (n == (long)BATCH * DDIM)        aspect = p;
        else if (n == 2 * DDIM)                  W      = p;
        else if (n == 1)                         bias   = p;
    }

    att_fused<<<NBLK, 256>>>(memory, aspect, W, bias, (float*)d_out);
}

// round 12
// speedup vs baseline: 1.1223x; 1.1223x over previous
#include <cuda_runtime.h>
#include <cuda_bf16.h>

// Problem dims
#define BATCH  64
#define SDIM   4096
#define DDIM   256
#define SCHUNK 512
#define NCHUNK (SDIM / SCHUNK)          // 8
#define NBLK   (BATCH * NCHUNK)         // 512 CTAs, occ 4, single wave

// Scratch for cross-CTA partials (no allocation allowed -> device globals)
__device__ float g_acc[NBLK * DDIM];    // 512 KB
__device__ float g_sum[NBLK];
__device__ int   g_cnt[BATCH];          // zero-init; re-armed by finalizer each run

__device__ __forceinline__ float warp_sum(float v) {
    #pragma unroll
    for (int o = 16; o; o >>= 1) v += __shfl_xor_sync(0xffffffffu, v, o);
    return v;
}

// exp(tanh(x)) via tanh(x) = 1 - 2/(e^{2x}+1); saturates correctly at +-1.
// Validated at rel_err 1.01e-6 in R9/R10 (same as tanhf path).
__device__ __forceinline__ float exp_tanh(float x) {
    const float t  = __expf(2.f * x);
    const float th = 1.f - __fdividef(2.f, t + 1.f);
    return __expf(th);
}

__device__ __forceinline__ float dot8(const float4& m0, const float4& m1,
                                      const float4& w0, const float4& w1) {
    return m0.x * w0.x + m0.y * w0.y + m0.z * w0.z + m0.w * w0.w
         + m1.x * w1.x + m1.y * w1.y + m1.z * w1.z + m1.w * w1.w;
}

// ---------------------------------------------------------------------------
// Single pass over memory (268 MB read exactly once):
//   gi = tanh(m·Wm + c_b) in [-1,1] => exp never overflows => softmax needs
//   no running max; accumulate exp(gi)*m and exp(gi) in one sweep.
// R4 structure (best measured: 5.88 TB/s) + trims: streaming loads (__ldcs,
// zero-reuse data should not occupy L2), short activation chain, and a
// deterministic epilogue. Last CTA per batch finalizes the output.
// ---------------------------------------------------------------------------
__global__ __launch_bounds__(256, 4)
void att_fused(const float* __restrict__ memory,
               const float* __restrict__ aspect,
               const float* __restrict__ W,
               const float* __restrict__ bias,
               float* __restrict__ out)
{
    __shared__ float slab[8][DDIM];      // per-warp partial vectors (8 KB)
    __shared__ float wred[8];
    __shared__ float wsum[8];
    __shared__ float sc;
    __shared__ int   s_old;

    const int tid  = threadIdx.x;
    const int lane = tid & 31;
    const int warp = tid >> 5;
    const int blk  = blockIdx.x;
    const int b    = blk >> 3;           // / NCHUNK
    const int chnk = blk & (NCHUNK - 1);

    // ---- c_b = aspect[b]·Wa + bias (deterministic combine) ----
    {
        float v = warp_sum(aspect[b * DDIM + tid] * W[DDIM + tid]);
        if (lane == 0) wred[warp] = v;
        __syncthreads();
        if (tid == 0) {
            float c = bias[0];
            #pragma unroll
            for (int w = 0; w < 8; w++) c += wred[w];
            sc = c;
        }
        __syncthreads();
    }
    const float cb = sc;

    // ---- Wm slice in registers: lane covers d = 4*lane.. and 128+4*lane.. ----
    const float4 wm0 = *reinterpret_cast<const float4*>(W + 4 * lane);
    const float4 wm1 = *reinterpret_cast<const float4*>(W + 128 + 4 * lane);

    float4 a0 = make_float4(0.f, 0.f, 0.f, 0.f);
    float4 a1 = make_float4(0.f, 0.f, 0.f, 0.f);
    float  sw = 0.f;

    const float4* base = reinterpret_cast<const float4*>(
        memory + ((long)b * SDIM + (long)chnk * SCHUNK) * DDIM);
    // row r occupies float4s [r*64, r*64+64); this warp does r = warp + 8*i
    const float4* p = base + (long)warp * 64;
    const long rstep = 8 * 64;           // 8 rows ahead per i

    // prologue: rows i=0,1 (evict-first streaming loads — data has no reuse)
    float4 c00 = __ldcs(p + lane),             c01 = __ldcs(p + 32 + lane);
    float4 c10 = __ldcs(p + rstep + lane),     c11 = __ldcs(p + rstep + 32 + lane);

    #pragma unroll 2
    for (int i = 0; i < 64; i += 2) {
        // ---- prefetch rows i+2, i+3 (guarded; dead on last iter) ----
        float4 n00, n01, n10, n11;
        if (i + 2 < 64) {
            const float4* q = p + (long)(i + 2) * rstep;
            n00 = __ldcs(q + lane);          n01 = __ldcs(q + 32 + lane);
            n10 = __ldcs(q + rstep + lane);  n11 = __ldcs(q + rstep + 32 + lane);
        }

        // ---- two independent dot/reduce/activation chains ----
        float d0 = warp_sum(dot8(c00, c01, wm0, wm1));
        float d1 = warp_sum(dot8(c10, c11, wm0, wm1));
        const float w0 = exp_tanh(d0 + cb);
        const float w1 = exp_tanh(d1 + cb);

        a0.x += w0 * c00.x + w1 * c10.x;  a0.y += w0 * c00.y + w1 * c10.y;
        a0.z += w0 * c00.z + w1 * c10.z;  a0.w += w0 * c00.w + w1 * c10.w;
        a1.x += w0 * c01.x + w1 * c11.x;  a1.y += w0 * c01.y + w1 * c11.y;
        a1.z += w0 * c01.z + w1 * c11.z;  a1.w += w0 * c01.w + w1 * c11.w;
        sw   += w0 + w1;                  // uniform across lanes post-butterfly

        c00 = n00; c01 = n01; c10 = n10; c11 = n11;
    }

    // ---- deterministic 8-warp combine via slab ----
    float* my = &slab[warp][0];
    my[4 * lane + 0] = a0.x;  my[4 * lane + 1] = a0.y;
    my[4 * lane + 2] = a0.z;  my[4 * lane + 3] = a0.w;
    my[128 + 4 * lane + 0] = a1.x;  my[128 + 4 * lane + 1] = a1.y;
    my[128 + 4 * lane + 2] = a1.z;  my[128 + 4 * lane + 3] = a1.w;
    if (lane == 0) wsum[warp] = sw;
    __syncthreads();

    {
        float t = 0.f;
        #pragma unroll
        for (int w = 0; w < 8; w++) t += slab[w][tid];
        g_acc[blk * DDIM + tid] = t;
        if (tid == 0) {
            float s = 0.f;
            #pragma unroll
            for (int w = 0; w < 8; w++) s += wsum[w];
            g_sum[blk] = s;
        }
    }
    __syncthreads();

    // ---- last-CTA-per-batch finalize (threadfence-reduction pattern) ----
    if (tid == 0) {
        __threadfence();
        s_old = atomicAdd(&g_cnt[b], 1);
    }
    __syncthreads();
    if (s_old == NCHUNK - 1) {
        __threadfence();                  // acquire siblings' partials
        float acc = 0.f, s = 0.f;
        #pragma unroll
        for (int c = 0; c < NCHUNK; c++) {
            acc += g_acc[(b * NCHUNK + c) * DDIM + tid];
            s   += g_sum[b * NCHUNK + c];
        }
        out[b * DDIM + tid] = acc * __fdividef(1.f, s);
        __syncthreads();
        if (tid == 0) g_cnt[b] = 0;       // re-arm for next graph replay
    }
}

extern "C" void kernel_launch(void* const* d_in, const int* in_sizes, int n_in,
                              void* d_out, int out_size)
{
    // Map inputs by element count:
    //   memory: B*S*D = 67108864, aspect: B*D = 16384, W: 2*D = 512, b: 1
    const float *aspect = nullptr, *memory = nullptr, *W = nullptr, *bias = nullptr;
    for (int i = 0; i < n_in; i++) {
        const long n = (long)in_sizes[i];
        const float* p = (const float*)d_in[i];
        if      (n == (long)BATCH * SDIM * DDIM) memory = p;
        else if (n == (long)BATCH * DDIM)        aspect = p;
        else if (n == 2 * DDIM)                  W      = p;
        else if (n == 1)                         bias   = p;
    }

    att_fused<<<NBLK, 256>>>(memory, aspect, W, bias, (float*)d_out);
}